// round 1
// baseline (speedup 1.0000x reference)
#include <cuda_runtime.h>

// Problem constants (fixed shapes from reference)
#define B_   256
#define P_   4
#define D_   768
#define U_   32
#define IN_  3072   // P_*D_

// ---------------------------------------------------------------------------
// Batched SGEMM: for u in [0,32): C[u] = A[256,3072] @ W[u][3072,768] + b[u]
// Tiles: BM=128, BN=128, BK=8. 256 threads, each computes 8x8.
// ---------------------------------------------------------------------------
#define BM 128
#define BN 128
#define BK 8
#define TM 8
#define TN 8

__global__ __launch_bounds__(256, 2)
void coldprompt_gemm(const float* __restrict__ A,      // [B_, IN_]
                     const float* __restrict__ W,      // [U_, IN_, D_]
                     const float* __restrict__ bias,   // [U_, D_]
                     float* __restrict__ C)            // [U_*B_, D_]
{
    __shared__ float As[BK][BM + 4];   // transposed A tile, padded vs STS conflicts
    __shared__ float Bs[BK][BN];

    const int u  = blockIdx.z;
    const int m0 = blockIdx.y * BM;
    const int n0 = blockIdx.x * BN;
    const float* __restrict__ Wu = W + (size_t)u * IN_ * D_;

    const int tid = threadIdx.x;
    const int tx  = tid & 15;   // n direction (16)
    const int ty  = tid >> 4;   // m direction (16)

    // Global-load mapping
    const int a_row = tid >> 1;          // 0..127
    const int a_col = (tid & 1) * 4;     // 0 or 4
    const int b_row = tid >> 5;          // 0..7
    const int b_col = (tid & 31) * 4;    // 0..124

    float acc[TM][TN];
    #pragma unroll
    for (int i = 0; i < TM; i++)
        #pragma unroll
        for (int j = 0; j < TN; j++)
            acc[i][j] = 0.0f;

    const float* Aptr = A + (size_t)(m0 + a_row) * IN_ + a_col;
    const float* Bptr = Wu + (size_t)b_row * D_ + n0 + b_col;

    for (int k0 = 0; k0 < IN_; k0 += BK) {
        float4 av = *(const float4*)(Aptr + k0);
        As[a_col + 0][a_row] = av.x;
        As[a_col + 1][a_row] = av.y;
        As[a_col + 2][a_row] = av.z;
        As[a_col + 3][a_row] = av.w;

        float4 bv = *(const float4*)(Bptr + (size_t)k0 * D_);
        *(float4*)&Bs[b_row][b_col] = bv;

        __syncthreads();

        #pragma unroll
        for (int k = 0; k < BK; k++) {
            float ra[TM], rb[TN];
            // broadcast-friendly LDS.128 reads
            *(float4*)&ra[0] = *(const float4*)&As[k][ty * TM + 0];
            *(float4*)&ra[4] = *(const float4*)&As[k][ty * TM + 4];
            *(float4*)&rb[0] = *(const float4*)&Bs[k][tx * TN + 0];
            *(float4*)&rb[4] = *(const float4*)&Bs[k][tx * TN + 4];
            #pragma unroll
            for (int i = 0; i < TM; i++)
                #pragma unroll
                for (int j = 0; j < TN; j++)
                    acc[i][j] = fmaf(ra[i], rb[j], acc[i][j]);
        }
        __syncthreads();
    }

    // Epilogue: add bias, store
    float bsv[TN];
    *(float4*)&bsv[0] = *(const float4*)&bias[u * D_ + n0 + tx * TN + 0];
    *(float4*)&bsv[4] = *(const float4*)&bias[u * D_ + n0 + tx * TN + 4];

    #pragma unroll
    for (int i = 0; i < TM; i++) {
        const int m = m0 + ty * TM + i;
        float* crow = C + ((size_t)u * B_ + m) * D_ + n0 + tx * TN;
        float4 v0, v1;
        v0.x = acc[i][0] + bsv[0];
        v0.y = acc[i][1] + bsv[1];
        v0.z = acc[i][2] + bsv[2];
        v0.w = acc[i][3] + bsv[3];
        v1.x = acc[i][4] + bsv[4];
        v1.y = acc[i][5] + bsv[5];
        v1.z = acc[i][6] + bsv[6];
        v1.w = acc[i][7] + bsv[7];
        *(float4*)(crow + 0) = v0;
        *(float4*)(crow + 4) = v1;
    }
}

// ---------------------------------------------------------------------------
// mean_emb[b, d] = mean_p weight[b, p, d]   (vectorized float4)
// ---------------------------------------------------------------------------
__global__ void coldprompt_mean(const float* __restrict__ w, float* __restrict__ out)
{
    const int n4 = (B_ * D_) / 4;
    int i = blockIdx.x * blockDim.x + threadIdx.x;
    if (i >= n4) return;
    const int d4_per_row = D_ / 4;            // 192
    const int b  = i / d4_per_row;
    const int d4 = i % d4_per_row;

    const float4* wp = (const float4*)w;
    float4 s = make_float4(0.f, 0.f, 0.f, 0.f);
    #pragma unroll
    for (int p = 0; p < P_; p++) {
        float4 v = wp[(size_t)(b * P_ + p) * d4_per_row + d4];
        s.x += v.x; s.y += v.y; s.z += v.z; s.w += v.w;
    }
    s.x *= 0.25f; s.y *= 0.25f; s.z *= 0.25f; s.w *= 0.25f;
    ((float4*)out)[i] = s;
}

extern "C" void kernel_launch(void* const* d_in, const int* in_sizes, int n_in,
                              void* d_out, int out_size)
{
    const float* weight = (const float*)d_in[0];   // [B_, P_, D_]
    const float* W_spec = (const float*)d_in[1];   // [U_, IN_, D_]
    const float* b_spec = (const float*)d_in[2];   // [U_, D_]
    float* out = (float*)d_out;

    // task_specific: out[0 .. U_*B_*D_)
    dim3 grid(D_ / BN, B_ / BM, U_);               // (6, 2, 32)
    coldprompt_gemm<<<grid, 256>>>(weight, W_spec, b_spec, out);

    // mean_emb: out[U_*B_*D_ .. U_*B_*D_ + B_*D_)
    const int n4 = (B_ * D_) / 4;
    coldprompt_mean<<<(n4 + 255) / 256, 256>>>(weight, out + (size_t)U_ * B_ * D_);
}

// round 3
// speedup vs baseline: 2.7033x; 2.7033x over previous
#include <cuda_runtime.h>
#include <cuda_bf16.h>
#include <cstdint>

#define B_   256
#define P_   4
#define D_   768
#define U_   32
#define IN_  3072

#define BM 128
#define BN 128
#define BK 32
#define NITER (IN_ / BK)   // 96
#define THREADS 256

// smem layout (bytes), per stage:
//   A_hi [128][40]bf16 = 10240 | A_lo 10240 | B_hi [32][136]bf16 = 8704 | B_lo 8704
#define ST_A_HI 0
#define ST_A_LO 10240
#define ST_B_HI 20480
#define ST_B_LO 29184
#define STAGE_SZ 37888
#define SMEM_TOTAL (2 * STAGE_SZ)   // 75776
#define A_STRIDE 40   // bf16 elems per A row (80B)
#define B_STRIDE 136  // bf16 elems per B row (272B)

__device__ __forceinline__ uint32_t smem_u32(const void* p) {
    uint32_t a;
    asm("{ .reg .u64 t; cvta.to.shared.u64 t, %1; cvt.u32.u64 %0, t; }" : "=r"(a) : "l"(p));
    return a;
}

#define LDSM_X4(r, addr) \
    asm volatile("ldmatrix.sync.aligned.m8n8.x4.shared.b16 {%0,%1,%2,%3}, [%4];" \
        : "=r"((r)[0]), "=r"((r)[1]), "=r"((r)[2]), "=r"((r)[3]) : "r"(addr))
#define LDSM_X4T(r, addr) \
    asm volatile("ldmatrix.sync.aligned.m8n8.x4.trans.shared.b16 {%0,%1,%2,%3}, [%4];" \
        : "=r"((r)[0]), "=r"((r)[1]), "=r"((r)[2]), "=r"((r)[3]) : "r"(addr))

#define MMA16816(d, a, b0, b1) \
    asm volatile("mma.sync.aligned.m16n8k16.row.col.f32.bf16.bf16.f32 " \
        "{%0,%1,%2,%3}, {%4,%5,%6,%7}, {%8,%9}, {%0,%1,%2,%3};" \
        : "+f"((d)[0]), "+f"((d)[1]), "+f"((d)[2]), "+f"((d)[3]) \
        : "r"((a)[0]), "r"((a)[1]), "r"((a)[2]), "r"((a)[3]), "r"(b0), "r"(b1))

__device__ __forceinline__ uint32_t pack2(__nv_bfloat16 a, __nv_bfloat16 b) {
    return (uint32_t)__bfloat16_as_ushort(a) | ((uint32_t)__bfloat16_as_ushort(b) << 16);
}
__device__ __forceinline__ void cvt_hilo(float x, float y, uint32_t& hi, uint32_t& lo) {
    __nv_bfloat16 hx = __float2bfloat16(x);
    __nv_bfloat16 hy = __float2bfloat16(y);
    __nv_bfloat16 lx = __float2bfloat16(x - __bfloat162float(hx));
    __nv_bfloat16 ly = __float2bfloat16(y - __bfloat162float(hy));
    hi = pack2(hx, hy);
    lo = pack2(lx, ly);
}

__global__ void __launch_bounds__(THREADS, 1)
coldprompt_mma_gemm(const float* __restrict__ A,     // [256, 3072]
                    const float* __restrict__ W,     // [32, 3072, 768]
                    const float* __restrict__ bias,  // [32, 768]
                    float* __restrict__ C)           // [32*256, 768]
{
    extern __shared__ char smem[];
    const uint32_t sb = smem_u32(smem);

    const int tid  = threadIdx.x;
    const int wid  = tid >> 5;
    const int lane = tid & 31;
    const int u    = blockIdx.z;
    const int m0   = blockIdx.y * BM;
    const int n0   = blockIdx.x * BN;

    const int wm = (wid >> 2) * 64;   // warp m offset in CTA tile
    const int wn = (wid & 3) * 32;    // warp n offset

    // global load mapping
    const int a_m  = tid >> 3;            // +32*c later? no: idx-based below
    const float* __restrict__ Abase = A + (size_t)m0 * IN_;
    const float* __restrict__ Wbase = W + (size_t)u * IN_ * D_ + n0;

    float acc[4][4][4];
    #pragma unroll
    for (int i = 0; i < 4; i++)
        #pragma unroll
        for (int j = 0; j < 4; j++)
            #pragma unroll
            for (int k = 0; k < 4; k++)
                acc[i][j][k] = 0.0f;

    float4 ra[4], rb[4];

    // ---- helpers as lambdas ----
    auto LOAD = [&](int it) {
        const int k0 = it * BK;
        #pragma unroll
        for (int c = 0; c < 4; ++c) {
            const int idx = tid + THREADS * c;
            const int m  = idx >> 3;
            const int kq = (idx & 7) * 4;
            ra[c] = *(const float4*)(Abase + (size_t)m * IN_ + k0 + kq);
        }
        #pragma unroll
        for (int c = 0; c < 4; ++c) {
            const int idx = tid + THREADS * c;
            const int kr = idx >> 5;
            const int n  = (idx & 31) * 4;
            rb[c] = *(const float4*)(Wbase + (size_t)(k0 + kr) * D_ + n);
        }
    };

    auto STORE = [&](int s) {
        char* st = smem + s * STAGE_SZ;
        #pragma unroll
        for (int c = 0; c < 4; ++c) {
            const int idx = tid + THREADS * c;
            const int m  = idx >> 3;
            const int kq = (idx & 7) * 4;
            uint32_t h0, l0, h1, l1;
            cvt_hilo(ra[c].x, ra[c].y, h0, l0);
            cvt_hilo(ra[c].z, ra[c].w, h1, l1);
            char* pa = st + ST_A_HI + (m * A_STRIDE + kq) * 2;
            *(uint2*)pa = make_uint2(h0, h1);
            *(uint2*)(pa + (ST_A_LO - ST_A_HI)) = make_uint2(l0, l1);
        }
        #pragma unroll
        for (int c = 0; c < 4; ++c) {
            const int idx = tid + THREADS * c;
            const int kr = idx >> 5;
            const int n  = (idx & 31) * 4;
            uint32_t h0, l0, h1, l1;
            cvt_hilo(rb[c].x, rb[c].y, h0, l0);
            cvt_hilo(rb[c].z, rb[c].w, h1, l1);
            char* pb = st + ST_B_HI + (kr * B_STRIDE + n) * 2;
            *(uint2*)pb = make_uint2(h0, h1);
            *(uint2*)(pb + (ST_B_LO - ST_B_HI)) = make_uint2(l0, l1);
        }
    };

    // ldmatrix address components (constant across iterations)
    const uint32_t a_row  = wm + (lane & 15);
    const uint32_t a_kofs = (lane >> 4) * 8;
    const uint32_t b_krow = (lane & 7) + ((lane >> 3) & 1) * 8;
    const uint32_t b_ncol = wn + (lane >> 4) * 8;

    auto COMPUTE = [&](int s) {
        const uint32_t st = sb + s * STAGE_SZ;
        #pragma unroll
        for (int ks = 0; ks < 2; ++ks) {
            uint32_t a_hi[4][4], a_lo[4][4];
            #pragma unroll
            for (int mt = 0; mt < 4; ++mt) {
                const uint32_t arow = (a_row + mt * 16) * A_STRIDE;
                const uint32_t ak   = ks * 16 + a_kofs;
                LDSM_X4(a_hi[mt], st + ST_A_HI + (arow + ak) * 2);
                LDSM_X4(a_lo[mt], st + ST_A_LO + (arow + ak) * 2);
            }
            uint32_t b_hi[8], b_lo[8];
            #pragma unroll
            for (int nt2 = 0; nt2 < 2; ++nt2) {
                const uint32_t baddr =
                    ((ks * 16 + b_krow) * B_STRIDE + b_ncol + nt2 * 16) * 2;
                LDSM_X4T(&b_hi[nt2 * 4], st + ST_B_HI + baddr);
                LDSM_X4T(&b_lo[nt2 * 4], st + ST_B_LO + baddr);
            }
            #pragma unroll
            for (int mt = 0; mt < 4; ++mt) {
                #pragma unroll
                for (int nt = 0; nt < 4; ++nt) {
                    MMA16816(acc[mt][nt], a_hi[mt], b_hi[nt * 2], b_hi[nt * 2 + 1]);
                    MMA16816(acc[mt][nt], a_hi[mt], b_lo[nt * 2], b_lo[nt * 2 + 1]);
                    MMA16816(acc[mt][nt], a_lo[mt], b_hi[nt * 2], b_hi[nt * 2 + 1]);
                }
            }
        }
    };

    // ---- pipeline ----
    LOAD(0);
    STORE(0);
    __syncthreads();

    #pragma unroll 1
    for (int it = 0; it < NITER; ++it) {
        if (it + 1 < NITER) LOAD(it + 1);
        COMPUTE(it & 1);
        if (it + 1 < NITER) {
            __syncthreads();
            STORE((it + 1) & 1);
            __syncthreads();
        }
    }

    // ---- epilogue ----
    const int g  = lane >> 2;
    const int tq = lane & 3;
    #pragma unroll
    for (int mt = 0; mt < 4; ++mt) {
        #pragma unroll
        for (int nt = 0; nt < 4; ++nt) {
            const int row0 = m0 + wm + mt * 16 + g;
            const int col  = n0 + wn + nt * 8 + tq * 2;
            const float2 bv = *(const float2*)(bias + (size_t)u * D_ + col);
            float* c0 = C + ((size_t)u * B_ + row0) * D_ + col;
            float* c1 = c0 + (size_t)8 * D_;
            float2 o0, o1;
            o0.x = acc[mt][nt][0] + bv.x;
            o0.y = acc[mt][nt][1] + bv.y;
            o1.x = acc[mt][nt][2] + bv.x;
            o1.y = acc[mt][nt][3] + bv.y;
            *(float2*)c0 = o0;
            *(float2*)c1 = o1;
        }
    }
}

// ---------------- mean_emb ----------------
__global__ void coldprompt_mean(const float* __restrict__ w, float* __restrict__ out)
{
    const int n4 = (B_ * D_) / 4;
    int i = blockIdx.x * blockDim.x + threadIdx.x;
    if (i >= n4) return;
    const int d4_per_row = D_ / 4;
    const int b  = i / d4_per_row;
    const int d4 = i % d4_per_row;
    const float4* wp = (const float4*)w;
    float4 s = make_float4(0.f, 0.f, 0.f, 0.f);
    #pragma unroll
    for (int p = 0; p < P_; p++) {
        float4 v = wp[(size_t)(b * P_ + p) * d4_per_row + d4];
        s.x += v.x; s.y += v.y; s.z += v.z; s.w += v.w;
    }
    s.x *= 0.25f; s.y *= 0.25f; s.z *= 0.25f; s.w *= 0.25f;
    ((float4*)out)[i] = s;
}

extern "C" void kernel_launch(void* const* d_in, const int* in_sizes, int n_in,
                              void* d_out, int out_size)
{
    const float* weight = (const float*)d_in[0];
    const float* W_spec = (const float*)d_in[1];
    const float* b_spec = (const float*)d_in[2];
    float* out = (float*)d_out;

    cudaFuncSetAttribute(coldprompt_mma_gemm,
                         cudaFuncAttributeMaxDynamicSharedMemorySize, SMEM_TOTAL);

    dim3 grid(D_ / BN, B_ / BM, U_);   // (6, 2, 32)
    coldprompt_mma_gemm<<<grid, THREADS, SMEM_TOTAL>>>(weight, W_spec, b_spec, out);

    const int n4 = (B_ * D_) / 4;
    coldprompt_mean<<<(n4 + 255) / 256, 256>>>(weight, out + (size_t)U_ * B_ * D_);
}